// round 16
// baseline (speedup 1.0000x reference)
#include <cuda_runtime.h>
#include <cuda_fp16.h>
#include <cstdint>

// Problem constants
#define B_ 4
#define S_ 2048
#define E_ 768
#define H_ 12
#define D_ 64
#define SCALE_ 0.125f   // 1/sqrt(64)

// Scratch (no cudaMalloc allowed). Natural row-major layouts.
__device__ __align__(16) __half g_x[(size_t)B_ * S_ * E_];         // [m][k]
__device__ __align__(16) __half g_w[(size_t)3 * E_ * E_];          // W^T [n][k]
__device__ __align__(16) __half g_q[(size_t)B_ * H_ * S_ * D_];    // [bh][s][d], pre-scaled 1/8
__device__ __align__(16) __half g_k[(size_t)B_ * H_ * S_ * D_];    // [bh][s][d]
__device__ __align__(16) __half g_v[(size_t)B_ * H_ * S_ * D_];    // [bh][s][d]

// ---------------------------------------------------------------------------
// helpers
// ---------------------------------------------------------------------------
__device__ __forceinline__ uint32_t packh2(float lo, float hi) {
    __half2 h = __floats2half2_rn(lo, hi);
    return *reinterpret_cast<uint32_t*>(&h);
}

__device__ __forceinline__ uint32_t hmax2z(uint32_t x) {
    uint32_t r;
    asm("max.f16x2 %0, %1, %2;" : "=r"(r) : "r"(x), "r"(0u));
    return r;
}

__device__ __forceinline__ void mma16(float c[4],
                                      uint32_t a0, uint32_t a1, uint32_t a2, uint32_t a3,
                                      uint32_t b0, uint32_t b1) {
    asm volatile(
        "mma.sync.aligned.m16n8k16.row.col.f32.f16.f16.f32 "
        "{%0,%1,%2,%3}, {%4,%5,%6,%7}, {%8,%9}, {%0,%1,%2,%3};"
        : "+f"(c[0]), "+f"(c[1]), "+f"(c[2]), "+f"(c[3])
        : "r"(a0), "r"(a1), "r"(a2), "r"(a3), "r"(b0), "r"(b1));
}

__device__ __forceinline__ void ldsm4(uint32_t& r0, uint32_t& r1,
                                      uint32_t& r2, uint32_t& r3, uint32_t addr) {
    asm volatile("ldmatrix.sync.aligned.m8n8.x4.shared.b16 {%0,%1,%2,%3}, [%4];"
                 : "=r"(r0), "=r"(r1), "=r"(r2), "=r"(r3) : "r"(addr));
}

__device__ __forceinline__ void ldsm4t(uint32_t& r0, uint32_t& r1,
                                       uint32_t& r2, uint32_t& r3, uint32_t addr) {
    asm volatile("ldmatrix.sync.aligned.m8n8.x4.trans.shared.b16 {%0,%1,%2,%3}, [%4];"
                 : "=r"(r0), "=r"(r1), "=r"(r2), "=r"(r3) : "r"(addr));
}

__device__ __forceinline__ void cp16(void* sdst, const void* gsrc) {
    uint32_t a = (uint32_t)__cvta_generic_to_shared(sdst);
    asm volatile("cp.async.cg.shared.global [%0], [%1], 16;"
                 :: "r"(a), "l"(gsrc));
}
#define CP_COMMIT() asm volatile("cp.async.commit_group;")
#define CP_WAIT0()  asm volatile("cp.async.wait_group 0;")

// SMEM row strides giving conflict-free ldmatrix (row advance ≡ 16B mod 128B):
#define AST 36               // 64-half rows (attn): 144 B
#define ROWB (AST * 4)
#define GST 68               // 128-half rows (gemm BK=128): 272 B
#define GROWB (GST * 4)

// per-lane ldmatrix byte offsets (parameterized row stride)
__device__ __forceinline__ uint32_t a_offs(int lane, int rowb) {
    return (uint32_t)((lane & 15) * rowb + ((lane & 16) ? 16 : 0));
}
__device__ __forceinline__ uint32_t b_offs(int lane, int rowb) {
    return (uint32_t)(((lane & 7) + ((lane & 16) >> 1)) * rowb +
                      ((lane & 8) ? 16 : 0));
}

// ---------------------------------------------------------------------------
// Prep: X f32 -> g_x fp16  AND  W [768][2304] f32 -> g_w = W^T fp16, fused.
// ---------------------------------------------------------------------------
#define NXBLK 6144    // (4*2048*768/4) / 256
__global__ void cvt_all(const float4* __restrict__ X4, const float* __restrict__ W)
{
    __shared__ float t[32][33];
    const int tid = threadIdx.x;
    if (blockIdx.x < NXBLK) {
        int i = blockIdx.x * 256 + tid;
        float4 v = X4[i];
        uint2 o = make_uint2(packh2(v.x, v.y), packh2(v.z, v.w));
        *reinterpret_cast<uint2*>(g_x + (size_t)i * 4) = o;
    } else {
        int bw = blockIdx.x - NXBLK;           // 0..1727
        int n0 = (bw % 72) * 32, k0 = (bw / 72) * 32;
        int tx = tid & 31, ty = tid >> 5;
        for (int i = ty; i < 32; i += 8)
            t[i][tx] = W[(size_t)(k0 + i) * (3 * E_) + n0 + tx];
        __syncthreads();
        for (int r = ty; r < 32; r += 8) {
            float v = t[tx][r];
            g_w[(size_t)(n0 + r) * E_ + k0 + tx] = __float2half_rn(v);
        }
    }
}

// ---------------------------------------------------------------------------
// Kernel 1: QKV projection. CTA tile 256x128, 512 threads = 16 warps (8m x 2n),
// warp 32x64, BK=128 (6 stages — barrier rounds halved vs BK=64),
// double-buffered cp.async, power-of-2 chunk addressing.
// ---------------------------------------------------------------------------
#define GEMM_A_W (256 * GST)
#define GEMM_B_W (128 * GST)
#define GEMM_SMEM_BYTES ((2 * GEMM_A_W + 2 * GEMM_B_W) * 4)   // 208896

__global__ __launch_bounds__(512, 1) void qkv_gemm(const float* __restrict__ bias)
{
    extern __shared__ uint32_t shg[];
    uint32_t* As = shg;                      // [2][256][68]
    uint32_t* Bs = shg + 2 * GEMM_A_W;       // [2][128][68]
    const uint32_t sbase = (uint32_t)__cvta_generic_to_shared(shg);
    const uint32_t boffB = 2 * GEMM_A_W * 4;

    const int tid  = threadIdx.x;
    const int lane = tid & 31;
    const int wid  = tid >> 5;
    const int g    = lane >> 2;
    const int tg   = lane & 3;
    const int wm   = wid & 7;     // 8 warp-rows, 32 rows each
    const int wn   = wid >> 3;    // 2 warp-cols, 64 cols each
    const int mbase = blockIdx.y * 256;
    const int nbase = blockIdx.x * 128;

    const uint32_t aoff = a_offs(lane, GROWB);
    const uint32_t boff = b_offs(lane, GROWB);

    float acc[2][8][4];
#pragma unroll
    for (int mi = 0; mi < 2; mi++)
#pragma unroll
        for (int ni = 0; ni < 8; ni++)
#pragma unroll
            for (int c = 0; c < 4; c++) acc[mi][ni][c] = 0.f;

    auto stage = [&](int buf, int k0) {
        uint32_t* Ab = As + buf * GEMM_A_W;
        uint32_t* Bb = Bs + buf * GEMM_B_W;
        // A: 256 rows x 16 chunks = 4096 -> 8 per thread
#pragma unroll
        for (int i = 0; i < 8; i++) {
            int j = i * 512 + tid;
            int r = j >> 4, c = j & 15;
            cp16(&Ab[r * GST + c * 4], g_x + (size_t)(mbase + r) * E_ + k0 + c * 8);
        }
        // B: 128 rows x 16 chunks = 2048 -> 4 per thread
#pragma unroll
        for (int i = 0; i < 4; i++) {
            int j = i * 512 + tid;
            int r = j >> 4, c = j & 15;
            cp16(&Bb[r * GST + c * 4], g_w + (size_t)(nbase + r) * E_ + k0 + c * 8);
        }
    };

    const int NK = E_ / 128;   // 6
    stage(0, 0);
    CP_COMMIT();

    for (int ks = 0; ks < NK; ks++) {
        CP_WAIT0();
        __syncthreads();
        if (ks + 1 < NK) {
            stage((ks + 1) & 1, (ks + 1) * 128);
            CP_COMMIT();
        }
        const uint32_t Aad = sbase + (ks & 1) * (GEMM_A_W * 4)
                           + (wm * 32) * GROWB + aoff;
        const uint32_t Bad = sbase + boffB + (ks & 1) * (GEMM_B_W * 4)
                           + (wn * 64) * GROWB + boff;

#pragma unroll
        for (int kk = 0; kk < 8; kk++) {
            uint32_t a[2][4];
#pragma unroll
            for (int mi = 0; mi < 2; mi++)
                ldsm4(a[mi][0], a[mi][1], a[mi][2], a[mi][3],
                      Aad + mi * (16 * GROWB) + kk * 32);
#pragma unroll
            for (int n2 = 0; n2 < 4; n2++) {
                uint32_t b0, b1, b2, b3;
                ldsm4(b0, b1, b2, b3, Bad + n2 * (16 * GROWB) + kk * 32);
#pragma unroll
                for (int mi = 0; mi < 2; mi++) {
                    mma16(acc[mi][2 * n2],     a[mi][0], a[mi][1], a[mi][2], a[mi][3], b0, b1);
                    mma16(acc[mi][2 * n2 + 1], a[mi][0], a[mi][1], a[mi][2], a[mi][3], b2, b3);
                }
            }
        }
    }

#pragma unroll
    for (int mi = 0; mi < 2; mi++) {
#pragma unroll
        for (int ni = 0; ni < 8; ni++) {
            int n = nbase + wn * 64 + ni * 8 + 2 * tg;
            int which = n / E_;
            int n2 = n - which * E_;
            int h = n2 >> 6, d = n2 & 63;
            float b0 = __ldg(bias + n), b1 = __ldg(bias + n + 1);
            __half* basep = (which == 0) ? g_q : ((which == 1) ? g_k : g_v);
#pragma unroll
            for (int half = 0; half < 2; half++) {
                int m = mbase + wm * 32 + mi * 16 + g + half * 8;
                int bb = m >> 11;
                int ss = m & 2047;
                float va = acc[mi][ni][half * 2 + 0] + b0;
                float vb = acc[mi][ni][half * 2 + 1] + b1;
                if (which == 0) { va *= SCALE_; vb *= SCALE_; }
                uint32_t pw = packh2(va, vb);
                size_t rowbase = (((size_t)bb * H_ + h) * S_ + ss);
                reinterpret_cast<uint32_t*>(basep + rowbase * D_)[d >> 1] = pw;
            }
        }
    }
}

// ---------------------------------------------------------------------------
// Kernel 2: causal ReLU attention (round-15 config — best known).
// fp16 mma + ldmatrix, K-super-tile 128, V transposed in-register,
// register S->P->Y dataflow, 2-deep ldsm prefetch pipelines, global LPT order.
// ---------------------------------------------------------------------------
#define QBYTES (128 * AST * 4)
#define KBUF   (128 * AST * 4)
#define VBUF   (128 * AST * 4)
#define KOFFB  QBYTES
#define VOFFB  (KOFFB + 2 * KBUF)
#define ATTN_SMEM_BYTES (VOFFB + 2 * VBUF)   // 92160

__global__ __launch_bounds__(256, 2) void attn_kernel(float* __restrict__ out)
{
    extern __shared__ uint32_t sh[];
    uint32_t* Qs = sh;
    uint32_t* Ks = Qs + 128 * AST;
    uint32_t* Vs = Ks + 2 * 128 * AST;
    const uint32_t sbase = (uint32_t)__cvta_generic_to_shared(sh);

    const int tid  = threadIdx.x;
    const int lane = tid & 31;
    const int w    = tid >> 5;
    const int g    = lane >> 2;
    const int tg   = lane & 3;

    // global LPT schedule: heaviest q-tiles first across all heads
    const int id = blockIdx.x;
    const int qt = 15 - (id / 48);
    const int bh = id % 48;
    const int qbase = qt * 128;

    const __half* Qg = g_q + ((size_t)bh * S_ + qbase) * D_;
    const __half* Kg = g_k + (size_t)bh * S_ * D_;
    const __half* Vg = g_v + (size_t)bh * S_ * D_;

    const uint32_t aoff  = a_offs(lane, ROWB);
    const uint32_t boffK = b_offs(lane, ROWB);

    auto stageKV = [&](int buf, int kt2) {
        uint32_t* Kb = Ks + buf * (128 * AST);
        uint32_t* Vb = Vs + buf * (128 * AST);
#pragma unroll
        for (int i = 0; i < 4; i++) {
            int jj = i * 256 + tid;
            int r = jj >> 3, c = jj & 7;
            size_t go = (size_t)(kt2 * 128 + r) * D_ + c * 8;
            cp16(&Kb[r * AST + c * 4], Kg + go);
            cp16(&Vb[r * AST + c * 4], Vg + go);
        }
    };

#pragma unroll
    for (int i = 0; i < 4; i++) {
        int jj = i * 256 + tid;
        int r = jj >> 3, c = jj & 7;
        cp16(&Qs[r * AST + c * 4], Qg + (size_t)r * D_ + c * 8);
    }
    stageKV(0, 0);
    CP_COMMIT();
    CP_WAIT0();
    __syncthreads();

    // hoist Q fragments (4 k16 groups)
    uint32_t qf[4][4];
    {
        const uint32_t Qad = sbase + (w * 16) * ROWB + aoff;
#pragma unroll
        for (int kk = 0; kk < 4; kk++)
            ldsm4(qf[kk][0], qf[kk][1], qf[kk][2], qf[kk][3], Qad + kk * 32);
    }

    float yacc[8][4];
#pragma unroll
    for (int ni = 0; ni < 8; ni++)
#pragma unroll
        for (int c = 0; c < 4; c++) yacc[ni][c] = 0.f;

    const int r0 = qbase + w * 16 + g;
    const int nkt2 = qt + 1;

    for (int kt2 = 0; kt2 < nkt2; kt2++) {
        if (kt2 > 0) {
            CP_WAIT0();
            __syncthreads();
        }
        if (kt2 + 1 < nkt2) {
            stageKV((kt2 + 1) & 1, kt2 + 1);
            CP_COMMIT();
        }
        const int buf = kt2 & 1;
        const uint32_t Kbase = sbase + KOFFB + buf * KBUF + boffK;
        const uint32_t Vbase = sbase + VOFFB + buf * VBUF + aoff;
        const bool diag = (kt2 == qt);

#pragma unroll
        for (int st = 0; st < 2; st++) {
            if (diag && (w * 16 + 15) < st * 64) continue;   // fully masked

            const uint32_t Kad = Kbase + st * (64 * ROWB);
            const uint32_t Vad = Vbase + st * (64 * ROWB);

            // ---- S = Q @ K^T : 2-deep ldsm prefetch pipeline ----
            float sacc[8][4];
#pragma unroll
            for (int ni = 0; ni < 8; ni++)
#pragma unroll
                for (int c = 0; c < 4; c++) sacc[ni][c] = 0.f;

            uint32_t kb[2][4];
            ldsm4(kb[0][0], kb[0][1], kb[0][2], kb[0][3], Kad);
#pragma unroll
            for (int it = 0; it < 16; it++) {
                const int kk = it >> 2, n2 = it & 3;
                const int cur = it & 1;
                if (it < 15) {
                    const int nx = it + 1;
                    ldsm4(kb[cur ^ 1][0], kb[cur ^ 1][1], kb[cur ^ 1][2], kb[cur ^ 1][3],
                          Kad + (nx & 3) * (16 * ROWB) + (nx >> 2) * 32);
                }
                mma16(sacc[2 * n2],     qf[kk][0], qf[kk][1], qf[kk][2], qf[kk][3],
                      kb[cur][0], kb[cur][1]);
                mma16(sacc[2 * n2 + 1], qf[kk][0], qf[kk][1], qf[kk][2], qf[kk][3],
                      kb[cur][2], kb[cur][3]);
            }

            // early V-frag issue: latency hides under pack ALU below
            uint32_t vb[2][4];
            ldsm4t(vb[0][0], vb[0][1], vb[0][2], vb[0][3], Vad);

            // ---- relu (+ mask on diagonal super-tile), pack to A-frags ----
            uint32_t pa[4][4];
            if (diag) {
                const int ktAbs = 2 * kt2 + st;
#pragma unroll
                for (int ni = 0; ni < 8; ni++) {
                    int c0 = ktAbs * 64 + ni * 8 + 2 * tg;
                    float v0 = fmaxf(sacc[ni][0], 0.f);
                    float v1 = fmaxf(sacc[ni][1], 0.f);
                    float v2 = fmaxf(sacc[ni][2], 0.f);
                    float v3 = fmaxf(sacc[ni][3], 0.f);
                    if (c0 > r0)         v0 = 0.f;
                    if (c0 + 1 > r0)     v1 = 0.f;
                    if (c0 > r0 + 8)     v2 = 0.f;
                    if (c0 + 1 > r0 + 8) v3 = 0.f;
                    sacc[ni][0] = v0; sacc[ni][1] = v1;
                    sacc[ni][2] = v2; sacc[ni][3] = v3;
                }
#pragma unroll
                for (int kk = 0; kk < 4; kk++) {
                    pa[kk][0] = packh2(sacc[2 * kk][0],     sacc[2 * kk][1]);
                    pa[kk][1] = packh2(sacc[2 * kk][2],     sacc[2 * kk][3]);
                    pa[kk][2] = packh2(sacc[2 * kk + 1][0], sacc[2 * kk + 1][1]);
                    pa[kk][3] = packh2(sacc[2 * kk + 1][2], sacc[2 * kk + 1][3]);
                }
            } else {
#pragma unroll
                for (int kk = 0; kk < 4; kk++) {
                    pa[kk][0] = hmax2z(packh2(sacc[2 * kk][0],     sacc[2 * kk][1]));
                    pa[kk][1] = hmax2z(packh2(sacc[2 * kk][2],     sacc[2 * kk][3]));
                    pa[kk][2] = hmax2z(packh2(sacc[2 * kk + 1][0], sacc[2 * kk + 1][1]));
                    pa[kk][3] = hmax2z(packh2(sacc[2 * kk + 1][2], sacc[2 * kk + 1][3]));
                }
            }

            // ---- Y += P @ V : 2-deep ldsm.trans prefetch pipeline ----
#pragma unroll
            for (int it = 0; it < 16; it++) {
                const int kk = it >> 2, n2 = it & 3;
                const int cur = it & 1;
                if (it < 15) {
                    const int nx = it + 1;
                    ldsm4t(vb[cur ^ 1][0], vb[cur ^ 1][1], vb[cur ^ 1][2], vb[cur ^ 1][3],
                           Vad + (nx >> 2) * (16 * ROWB) + (nx & 3) * 32);
                }
                mma16(yacc[2 * n2],     pa[kk][0], pa[kk][1], pa[kk][2], pa[kk][3],
                      vb[cur][0], vb[cur][1]);
                mma16(yacc[2 * n2 + 1], pa[kk][0], pa[kk][1], pa[kk][2], pa[kk][3],
                      vb[cur][2], vb[cur][3]);
            }
        }
    }

    // ---- write Y to out [B, S, H, D] ----
    const int b = bh / H_, h = bh % H_;
#pragma unroll
    for (int ni = 0; ni < 8; ni++) {
        int d0 = ni * 8 + 2 * tg;
        float2 v0 = make_float2(yacc[ni][0], yacc[ni][1]);
        *reinterpret_cast<float2*>(
            &out[(((size_t)b * S_ + r0) * H_ + h) * D_ + d0]) = v0;
        float2 v1 = make_float2(yacc[ni][2], yacc[ni][3]);
        *reinterpret_cast<float2*>(
            &out[(((size_t)b * S_ + r0 + 8) * H_ + h) * D_ + d0]) = v1;
    }
}

// ---------------------------------------------------------------------------
extern "C" void kernel_launch(void* const* d_in, const int* in_sizes, int n_in,
                              void* d_out, int out_size)
{
    const float* X    = (const float*)d_in[0];   // [4, 2048, 768]
    const float* W    = (const float*)d_in[1];   // [768, 2304]
    const float* bias = (const float*)d_in[2];   // [2304]
    float* out = (float*)d_out;                  // [4, 2048, 768]

    static bool attr_done = false;
    if (!attr_done) {
        cudaFuncSetAttribute(qkv_gemm,
                             cudaFuncAttributeMaxDynamicSharedMemorySize,
                             GEMM_SMEM_BYTES);
        cudaFuncSetAttribute(attn_kernel,
                             cudaFuncAttributeMaxDynamicSharedMemorySize,
                             ATTN_SMEM_BYTES);
        attr_done = true;
    }

    // fused prep: 6144 X blocks + 1728 W blocks
    cvt_all<<<NXBLK + (3 * E_ / 32) * (E_ / 32), 256>>>((const float4*)X, W);

    qkv_gemm<<<dim3(3 * E_ / 128, (B_ * S_) / 256), 512, GEMM_SMEM_BYTES>>>(bias);

    attn_kernel<<<(S_ / 128) * B_ * H_, 256, ATTN_SMEM_BYTES>>>(out);
}

// round 17
// speedup vs baseline: 1.0337x; 1.0337x over previous
#include <cuda_runtime.h>
#include <cuda_fp16.h>
#include <cstdint>

// Problem constants
#define B_ 4
#define S_ 2048
#define E_ 768
#define H_ 12
#define D_ 64
#define SCALE_ 0.125f   // 1/sqrt(64)

// Scratch (no cudaMalloc allowed). Natural row-major layouts.
__device__ __align__(16) __half g_x[(size_t)B_ * S_ * E_];         // [m][k]
__device__ __align__(16) __half g_w[(size_t)3 * E_ * E_];          // W^T [n][k]
__device__ __align__(16) __half g_q[(size_t)B_ * H_ * S_ * D_];    // [bh][s][d], pre-scaled 1/8
__device__ __align__(16) __half g_k[(size_t)B_ * H_ * S_ * D_];    // [bh][s][d]
__device__ __align__(16) __half g_v[(size_t)B_ * H_ * S_ * D_];    // [bh][s][d]

// ---------------------------------------------------------------------------
// helpers
// ---------------------------------------------------------------------------
__device__ __forceinline__ uint32_t packh2(float lo, float hi) {
    __half2 h = __floats2half2_rn(lo, hi);
    return *reinterpret_cast<uint32_t*>(&h);
}

__device__ __forceinline__ uint32_t hmax2z(uint32_t x) {
    uint32_t r;
    asm("max.f16x2 %0, %1, %2;" : "=r"(r) : "r"(x), "r"(0u));
    return r;
}

__device__ __forceinline__ void mma16(float c[4],
                                      uint32_t a0, uint32_t a1, uint32_t a2, uint32_t a3,
                                      uint32_t b0, uint32_t b1) {
    asm volatile(
        "mma.sync.aligned.m16n8k16.row.col.f32.f16.f16.f32 "
        "{%0,%1,%2,%3}, {%4,%5,%6,%7}, {%8,%9}, {%0,%1,%2,%3};"
        : "+f"(c[0]), "+f"(c[1]), "+f"(c[2]), "+f"(c[3])
        : "r"(a0), "r"(a1), "r"(a2), "r"(a3), "r"(b0), "r"(b1));
}

__device__ __forceinline__ void ldsm4(uint32_t& r0, uint32_t& r1,
                                      uint32_t& r2, uint32_t& r3, uint32_t addr) {
    asm volatile("ldmatrix.sync.aligned.m8n8.x4.shared.b16 {%0,%1,%2,%3}, [%4];"
                 : "=r"(r0), "=r"(r1), "=r"(r2), "=r"(r3) : "r"(addr));
}

__device__ __forceinline__ void ldsm4t(uint32_t& r0, uint32_t& r1,
                                       uint32_t& r2, uint32_t& r3, uint32_t addr) {
    asm volatile("ldmatrix.sync.aligned.m8n8.x4.trans.shared.b16 {%0,%1,%2,%3}, [%4];"
                 : "=r"(r0), "=r"(r1), "=r"(r2), "=r"(r3) : "r"(addr));
}

__device__ __forceinline__ void cp16(void* sdst, const void* gsrc) {
    uint32_t a = (uint32_t)__cvta_generic_to_shared(sdst);
    asm volatile("cp.async.cg.shared.global [%0], [%1], 16;"
                 :: "r"(a), "l"(gsrc));
}
#define CP_COMMIT() asm volatile("cp.async.commit_group;")
#define CP_WAIT0()  asm volatile("cp.async.wait_group 0;")

// SMEM row strides giving conflict-free ldmatrix (row advance ≡ 16B mod 128B):
#define AST 36               // 64-half rows (attn): 144 B
#define ROWB (AST * 4)
#define GST 68               // 128-half rows (gemm BK=128): 272 B
#define GROWB (GST * 4)
#define OST 136              // epilogue out-stage stride in halves (272 B)

// per-lane ldmatrix byte offsets (parameterized row stride)
__device__ __forceinline__ uint32_t a_offs(int lane, int rowb) {
    return (uint32_t)((lane & 15) * rowb + ((lane & 16) ? 16 : 0));
}
__device__ __forceinline__ uint32_t b_offs(int lane, int rowb) {
    return (uint32_t)(((lane & 7) + ((lane & 16) >> 1)) * rowb +
                      ((lane & 8) ? 16 : 0));
}

// ---------------------------------------------------------------------------
// Prep: X f32 -> g_x fp16  AND  W [768][2304] f32 -> g_w = W^T fp16, fused.
// ---------------------------------------------------------------------------
#define NXBLK 6144    // (4*2048*768/4) / 256
__global__ void cvt_all(const float4* __restrict__ X4, const float* __restrict__ W)
{
    __shared__ float t[32][33];
    const int tid = threadIdx.x;
    if (blockIdx.x < NXBLK) {
        int i = blockIdx.x * 256 + tid;
        float4 v = X4[i];
        uint2 o = make_uint2(packh2(v.x, v.y), packh2(v.z, v.w));
        *reinterpret_cast<uint2*>(g_x + (size_t)i * 4) = o;
    } else {
        int bw = blockIdx.x - NXBLK;           // 0..1727
        int n0 = (bw % 72) * 32, k0 = (bw / 72) * 32;
        int tx = tid & 31, ty = tid >> 5;
        for (int i = ty; i < 32; i += 8)
            t[i][tx] = W[(size_t)(k0 + i) * (3 * E_) + n0 + tx];
        __syncthreads();
        for (int r = ty; r < 32; r += 8) {
            float v = t[tx][r];
            g_w[(size_t)(n0 + r) * E_ + k0 + tx] = __float2half_rn(v);
        }
    }
}

// ---------------------------------------------------------------------------
// Kernel 1: QKV projection. CTA tile 256x128, 512 threads = 16 warps (8m x 2n),
// warp 32x64, BK=128 (6 stages), double-buffered cp.async.
// NEW: SMEM-restaged epilogue — coalesced uint4 output stores (the old direct
// scatter had ~8x write-sector amplification).
// ---------------------------------------------------------------------------
#define GEMM_A_W (256 * GST)
#define GEMM_B_W (128 * GST)
#define GEMM_SMEM_BYTES ((2 * GEMM_A_W + 2 * GEMM_B_W) * 4)   // 208896

__global__ __launch_bounds__(512, 1) void qkv_gemm(const float* __restrict__ bias)
{
    extern __shared__ uint32_t shg[];
    uint32_t* As = shg;                      // [2][256][68]
    uint32_t* Bs = shg + 2 * GEMM_A_W;       // [2][128][68]
    const uint32_t sbase = (uint32_t)__cvta_generic_to_shared(shg);
    const uint32_t boffB = 2 * GEMM_A_W * 4;

    const int tid  = threadIdx.x;
    const int lane = tid & 31;
    const int wid  = tid >> 5;
    const int g    = lane >> 2;
    const int tg   = lane & 3;
    const int wm   = wid & 7;     // 8 warp-rows, 32 rows each
    const int wn   = wid >> 3;    // 2 warp-cols, 64 cols each
    const int mbase = blockIdx.y * 256;
    const int nbase = blockIdx.x * 128;

    const uint32_t aoff = a_offs(lane, GROWB);
    const uint32_t boff = b_offs(lane, GROWB);

    float acc[2][8][4];
#pragma unroll
    for (int mi = 0; mi < 2; mi++)
#pragma unroll
        for (int ni = 0; ni < 8; ni++)
#pragma unroll
            for (int c = 0; c < 4; c++) acc[mi][ni][c] = 0.f;

    auto stage = [&](int buf, int k0) {
        uint32_t* Ab = As + buf * GEMM_A_W;
        uint32_t* Bb = Bs + buf * GEMM_B_W;
#pragma unroll
        for (int i = 0; i < 8; i++) {        // A: 256 rows x 16 chunks
            int j = i * 512 + tid;
            int r = j >> 4, c = j & 15;
            cp16(&Ab[r * GST + c * 4], g_x + (size_t)(mbase + r) * E_ + k0 + c * 8);
        }
#pragma unroll
        for (int i = 0; i < 4; i++) {        // B: 128 rows x 16 chunks
            int j = i * 512 + tid;
            int r = j >> 4, c = j & 15;
            cp16(&Bb[r * GST + c * 4], g_w + (size_t)(nbase + r) * E_ + k0 + c * 8);
        }
    };

    const int NK = E_ / 128;   // 6
    stage(0, 0);
    CP_COMMIT();

    for (int ks = 0; ks < NK; ks++) {
        CP_WAIT0();
        __syncthreads();
        if (ks + 1 < NK) {
            stage((ks + 1) & 1, (ks + 1) * 128);
            CP_COMMIT();
        }
        const uint32_t Aad = sbase + (ks & 1) * (GEMM_A_W * 4)
                           + (wm * 32) * GROWB + aoff;
        const uint32_t Bad = sbase + boffB + (ks & 1) * (GEMM_B_W * 4)
                           + (wn * 64) * GROWB + boff;

#pragma unroll
        for (int kk = 0; kk < 8; kk++) {
            uint32_t a[2][4];
#pragma unroll
            for (int mi = 0; mi < 2; mi++)
                ldsm4(a[mi][0], a[mi][1], a[mi][2], a[mi][3],
                      Aad + mi * (16 * GROWB) + kk * 32);
#pragma unroll
            for (int n2 = 0; n2 < 4; n2++) {
                uint32_t b0, b1, b2, b3;
                ldsm4(b0, b1, b2, b3, Bad + n2 * (16 * GROWB) + kk * 32);
#pragma unroll
                for (int mi = 0; mi < 2; mi++) {
                    mma16(acc[mi][2 * n2],     a[mi][0], a[mi][1], a[mi][2], a[mi][3], b0, b1);
                    mma16(acc[mi][2 * n2 + 1], a[mi][0], a[mi][1], a[mi][2], a[mi][3], b2, b3);
                }
            }
        }
    }

    // ---- Epilogue: restage through SMEM, then coalesced uint4 stores ----
    __syncthreads();                 // all ldsm reads of As/Bs complete
    __half* so = reinterpret_cast<__half*>(shg);   // reuse: [256][OST] halves

#pragma unroll
    for (int mi = 0; mi < 2; mi++) {
#pragma unroll
        for (int ni = 0; ni < 8; ni++) {
            int n_local = wn * 64 + ni * 8 + 2 * tg;
            int n = nbase + n_local;
            int which = n / E_;
            float b0 = __ldg(bias + n), b1 = __ldg(bias + n + 1);
#pragma unroll
            for (int half = 0; half < 2; half++) {
                int m_local = wm * 32 + mi * 16 + g + half * 8;
                float va = acc[mi][ni][half * 2 + 0] + b0;
                float vb = acc[mi][ni][half * 2 + 1] + b1;
                if (which == 0) { va *= SCALE_; vb *= SCALE_; }
                *reinterpret_cast<uint32_t*>(so + m_local * OST + n_local) =
                    packh2(va, vb);
            }
        }
    }
    __syncthreads();

    // coalesced copy: 256 rows x 16 uint4 = 4096 chunks, 8 per thread
#pragma unroll
    for (int i = 0; i < 8; i++) {
        int j = i * 512 + tid;
        int r = j >> 4, cc = j & 15;
        int n_local = cc * 8;
        int n = nbase + n_local;
        int which = n / E_;
        int n2 = n - which * E_;
        int h = n2 >> 6, d = n2 & 63;
        __half* basep = (which == 0) ? g_q : ((which == 1) ? g_k : g_v);
        int m = mbase + r;
        int bb = m >> 11;
        int ss = m & 2047;
        uint4 v = *reinterpret_cast<const uint4*>(so + r * OST + n_local);
        *reinterpret_cast<uint4*>(
            basep + (((size_t)bb * H_ + h) * S_ + ss) * D_ + d) = v;
    }
}

// ---------------------------------------------------------------------------
// Kernel 2: causal ReLU attention (round-15 config — best known).
// fp16 mma + ldmatrix, K-super-tile 128, V transposed in-register,
// register S->P->Y dataflow, 2-deep ldsm prefetch pipelines, global LPT order.
// ---------------------------------------------------------------------------
#define QBYTES (128 * AST * 4)
#define KBUF   (128 * AST * 4)
#define VBUF   (128 * AST * 4)
#define KOFFB  QBYTES
#define VOFFB  (KOFFB + 2 * KBUF)
#define ATTN_SMEM_BYTES (VOFFB + 2 * VBUF)   // 92160

__global__ __launch_bounds__(256, 2) void attn_kernel(float* __restrict__ out)
{
    extern __shared__ uint32_t sh[];
    uint32_t* Qs = sh;
    uint32_t* Ks = Qs + 128 * AST;
    uint32_t* Vs = Ks + 2 * 128 * AST;
    const uint32_t sbase = (uint32_t)__cvta_generic_to_shared(sh);

    const int tid  = threadIdx.x;
    const int lane = tid & 31;
    const int w    = tid >> 5;
    const int g    = lane >> 2;
    const int tg   = lane & 3;

    // global LPT schedule: heaviest q-tiles first across all heads
    const int id = blockIdx.x;
    const int qt = 15 - (id / 48);
    const int bh = id % 48;
    const int qbase = qt * 128;

    const __half* Qg = g_q + ((size_t)bh * S_ + qbase) * D_;
    const __half* Kg = g_k + (size_t)bh * S_ * D_;
    const __half* Vg = g_v + (size_t)bh * S_ * D_;

    const uint32_t aoff  = a_offs(lane, ROWB);
    const uint32_t boffK = b_offs(lane, ROWB);

    auto stageKV = [&](int buf, int kt2) {
        uint32_t* Kb = Ks + buf * (128 * AST);
        uint32_t* Vb = Vs + buf * (128 * AST);
#pragma unroll
        for (int i = 0; i < 4; i++) {
            int jj = i * 256 + tid;
            int r = jj >> 3, c = jj & 7;
            size_t go = (size_t)(kt2 * 128 + r) * D_ + c * 8;
            cp16(&Kb[r * AST + c * 4], Kg + go);
            cp16(&Vb[r * AST + c * 4], Vg + go);
        }
    };

#pragma unroll
    for (int i = 0; i < 4; i++) {
        int jj = i * 256 + tid;
        int r = jj >> 3, c = jj & 7;
        cp16(&Qs[r * AST + c * 4], Qg + (size_t)r * D_ + c * 8);
    }
    stageKV(0, 0);
    CP_COMMIT();
    CP_WAIT0();
    __syncthreads();

    // hoist Q fragments (4 k16 groups)
    uint32_t qf[4][4];
    {
        const uint32_t Qad = sbase + (w * 16) * ROWB + aoff;
#pragma unroll
        for (int kk = 0; kk < 4; kk++)
            ldsm4(qf[kk][0], qf[kk][1], qf[kk][2], qf[kk][3], Qad + kk * 32);
    }

    float yacc[8][4];
#pragma unroll
    for (int ni = 0; ni < 8; ni++)
#pragma unroll
        for (int c = 0; c < 4; c++) yacc[ni][c] = 0.f;

    const int r0 = qbase + w * 16 + g;
    const int nkt2 = qt + 1;

    for (int kt2 = 0; kt2 < nkt2; kt2++) {
        if (kt2 > 0) {
            CP_WAIT0();
            __syncthreads();
        }
        if (kt2 + 1 < nkt2) {
            stageKV((kt2 + 1) & 1, kt2 + 1);
            CP_COMMIT();
        }
        const int buf = kt2 & 1;
        const uint32_t Kbase = sbase + KOFFB + buf * KBUF + boffK;
        const uint32_t Vbase = sbase + VOFFB + buf * VBUF + aoff;
        const bool diag = (kt2 == qt);

#pragma unroll
        for (int st = 0; st < 2; st++) {
            if (diag && (w * 16 + 15) < st * 64) continue;   // fully masked

            const uint32_t Kad = Kbase + st * (64 * ROWB);
            const uint32_t Vad = Vbase + st * (64 * ROWB);

            // ---- S = Q @ K^T : 2-deep ldsm prefetch pipeline ----
            float sacc[8][4];
#pragma unroll
            for (int ni = 0; ni < 8; ni++)
#pragma unroll
                for (int c = 0; c < 4; c++) sacc[ni][c] = 0.f;

            uint32_t kb[2][4];
            ldsm4(kb[0][0], kb[0][1], kb[0][2], kb[0][3], Kad);
#pragma unroll
            for (int it = 0; it < 16; it++) {
                const int kk = it >> 2, n2 = it & 3;
                const int cur = it & 1;
                if (it < 15) {
                    const int nx = it + 1;
                    ldsm4(kb[cur ^ 1][0], kb[cur ^ 1][1], kb[cur ^ 1][2], kb[cur ^ 1][3],
                          Kad + (nx & 3) * (16 * ROWB) + (nx >> 2) * 32);
                }
                mma16(sacc[2 * n2],     qf[kk][0], qf[kk][1], qf[kk][2], qf[kk][3],
                      kb[cur][0], kb[cur][1]);
                mma16(sacc[2 * n2 + 1], qf[kk][0], qf[kk][1], qf[kk][2], qf[kk][3],
                      kb[cur][2], kb[cur][3]);
            }

            // early V-frag issue: latency hides under pack ALU below
            uint32_t vb[2][4];
            ldsm4t(vb[0][0], vb[0][1], vb[0][2], vb[0][3], Vad);

            // ---- relu (+ mask on diagonal super-tile), pack to A-frags ----
            uint32_t pa[4][4];
            if (diag) {
                const int ktAbs = 2 * kt2 + st;
#pragma unroll
                for (int ni = 0; ni < 8; ni++) {
                    int c0 = ktAbs * 64 + ni * 8 + 2 * tg;
                    float v0 = fmaxf(sacc[ni][0], 0.f);
                    float v1 = fmaxf(sacc[ni][1], 0.f);
                    float v2 = fmaxf(sacc[ni][2], 0.f);
                    float v3 = fmaxf(sacc[ni][3], 0.f);
                    if (c0 > r0)         v0 = 0.f;
                    if (c0 + 1 > r0)     v1 = 0.f;
                    if (c0 > r0 + 8)     v2 = 0.f;
                    if (c0 + 1 > r0 + 8) v3 = 0.f;
                    sacc[ni][0] = v0; sacc[ni][1] = v1;
                    sacc[ni][2] = v2; sacc[ni][3] = v3;
                }
#pragma unroll
                for (int kk = 0; kk < 4; kk++) {
                    pa[kk][0] = packh2(sacc[2 * kk][0],     sacc[2 * kk][1]);
                    pa[kk][1] = packh2(sacc[2 * kk][2],     sacc[2 * kk][3]);
                    pa[kk][2] = packh2(sacc[2 * kk + 1][0], sacc[2 * kk + 1][1]);
                    pa[kk][3] = packh2(sacc[2 * kk + 1][2], sacc[2 * kk + 1][3]);
                }
            } else {
#pragma unroll
                for (int kk = 0; kk < 4; kk++) {
                    pa[kk][0] = hmax2z(packh2(sacc[2 * kk][0],     sacc[2 * kk][1]));
                    pa[kk][1] = hmax2z(packh2(sacc[2 * kk][2],     sacc[2 * kk][3]));
                    pa[kk][2] = hmax2z(packh2(sacc[2 * kk + 1][0], sacc[2 * kk + 1][1]));
                    pa[kk][3] = hmax2z(packh2(sacc[2 * kk + 1][2], sacc[2 * kk + 1][3]));
                }
            }

            // ---- Y += P @ V : 2-deep ldsm.trans prefetch pipeline ----
#pragma unroll
            for (int it = 0; it < 16; it++) {
                const int kk = it >> 2, n2 = it & 3;
                const int cur = it & 1;
                if (it < 15) {
                    const int nx = it + 1;
                    ldsm4t(vb[cur ^ 1][0], vb[cur ^ 1][1], vb[cur ^ 1][2], vb[cur ^ 1][3],
                           Vad + (nx >> 2) * (16 * ROWB) + (nx & 3) * 32);
                }
                mma16(yacc[2 * n2],     pa[kk][0], pa[kk][1], pa[kk][2], pa[kk][3],
                      vb[cur][0], vb[cur][1]);
                mma16(yacc[2 * n2 + 1], pa[kk][0], pa[kk][1], pa[kk][2], pa[kk][3],
                      vb[cur][2], vb[cur][3]);
            }
        }
    }

    // ---- write Y to out [B, S, H, D] ----
    const int b = bh / H_, h = bh % H_;
#pragma unroll
    for (int ni = 0; ni < 8; ni++) {
        int d0 = ni * 8 + 2 * tg;
        float2 v0 = make_float2(yacc[ni][0], yacc[ni][1]);
        *reinterpret_cast<float2*>(
            &out[(((size_t)b * S_ + r0) * H_ + h) * D_ + d0]) = v0;
        float2 v1 = make_float2(yacc[ni][2], yacc[ni][3]);
        *reinterpret_cast<float2*>(
            &out[(((size_t)b * S_ + r0 + 8) * H_ + h) * D_ + d0]) = v1;
    }
}

// ---------------------------------------------------------------------------
extern "C" void kernel_launch(void* const* d_in, const int* in_sizes, int n_in,
                              void* d_out, int out_size)
{
    const float* X    = (const float*)d_in[0];   // [4, 2048, 768]
    const float* W    = (const float*)d_in[1];   // [768, 2304]
    const float* bias = (const float*)d_in[2];   // [2304]
    float* out = (float*)d_out;                  // [4, 2048, 768]

    static bool attr_done = false;
    if (!attr_done) {
        cudaFuncSetAttribute(qkv_gemm,
                             cudaFuncAttributeMaxDynamicSharedMemorySize,
                             GEMM_SMEM_BYTES);
        cudaFuncSetAttribute(attn_kernel,
                             cudaFuncAttributeMaxDynamicSharedMemorySize,
                             ATTN_SMEM_BYTES);
        attr_done = true;
    }

    // fused prep: 6144 X blocks + 1728 W blocks
    cvt_all<<<NXBLK + (3 * E_ / 32) * (E_ / 32), 256>>>((const float4*)X, W);

    qkv_gemm<<<dim3(3 * E_ / 128, (B_ * S_) / 256), 512, GEMM_SMEM_BYTES>>>(bias);

    attn_kernel<<<(S_ / 128) * B_ * H_, 256, ATTN_SMEM_BYTES>>>(out);
}